// round 2
// baseline (speedup 1.0000x reference)
#include <cuda_runtime.h>

// Problem constants (fixed shapes from reference):
//   B=4, H=512, W=512, K=8, BKG_DEPTH=100
// Inputs (metadata order):
//   d_in[0] pixel_colors  float32 [B,H,W,K,4]  = 33,554,432 elems
//   d_in[1] zbuf          float32 [B,H,W,K]    =  8,388,608 elems
//   d_in[2] pixel_labels  int32   [B,H,W,K]    =  8,388,608 elems
//   d_in[3] background    float32 [3]
// Output (flat float32, reference tuple order):
//   composite_image [B,H,W,4]  @ 0
//   composite_depth [B,H,W]    @ 4*NPIX
//   composite_label [B,H,W]    @ 5*NPIX   (int values stored as float)
//   human_images    [B,H,W,8,4]@ 6*NPIX

constexpr int   NPIX      = 4 * 512 * 512;       // 1,048,576 pixels
constexpr float BKG_DEPTH = 100.0f;

constexpr long long IMG_OFF   = 0;
constexpr long long DEPTH_OFF = (long long)NPIX * 4;
constexpr long long LABEL_OFF = DEPTH_OFF + NPIX;
constexpr long long HUMAN_OFF = LABEL_OFF + NPIX;

__global__ void __launch_bounds__(256)
alpha_composite_kernel(const float4* __restrict__ colors,   // [NPIX*8] float4
                       const float4* __restrict__ zbuf4,    // [NPIX*2] float4
                       const int4*   __restrict__ labl4,    // [NPIX*2] int4
                       const float*  __restrict__ bg,       // [3]
                       float*        __restrict__ out)
{
    const int p = blockIdx.x * blockDim.x + threadIdx.x;
    if (p >= NPIX) return;

    const float bgr = bg[0];
    const float bgg = bg[1];
    const float bgb = bg[2];

    // ---- load per-pixel data (all 128-bit loads) ----
    float4 c[8];
    const float4* cp = colors + (long long)p * 8;
#pragma unroll
    for (int k = 0; k < 8; ++k) c[k] = cp[k];

    float z[8];
    {
        float4 z0 = zbuf4[(long long)p * 2 + 0];
        float4 z1 = zbuf4[(long long)p * 2 + 1];
        z[0] = z0.x; z[1] = z0.y; z[2] = z0.z; z[3] = z0.w;
        z[4] = z1.x; z[5] = z1.y; z[6] = z1.z; z[7] = z1.w;
    }

    int lb[8];
    {
        int4 l0 = labl4[(long long)p * 2 + 0];
        int4 l1 = labl4[(long long)p * 2 + 1];
        lb[0] = l0.x; lb[1] = l0.y; lb[2] = l0.z; lb[3] = l0.w;
        lb[4] = l1.x; lb[5] = l1.y; lb[6] = l1.z; lb[7] = l1.w;
    }

    // ---- back-to-front composite scan (layer K-1 first, layer 0 last) ----
    float r = bgr, g = bgg, b = bgb;
    float a = 0.0f;
    float d = BKG_DEPTH;
    float labv = 8.0f;   // sentinel = K

#pragma unroll
    for (int k = 7; k >= 0; --k) {
        const float al = c[k].w;
        const float om = 1.0f - al;
        r = c[k].x * al + r * om;
        g = c[k].y * al + g * om;
        b = c[k].z * al + b * om;
        a = fmaxf(al, a);
        if (z[k] > 0.0f)                    d    = z[k] * al + d * om;
        if (z[k] >= 0.0f && al > 0.5f)      labv = (float)lb[k];   // z<0 => NaN label => keep
    }

    // composite image
    reinterpret_cast<float4*>(out + IMG_OFF)[p] = make_float4(r, g, b, a);
    // composite depth
    out[DEPTH_OFF + p] = d;
    // composite label: sentinel K -> -1
    out[LABEL_OFF + p] = (labv > 7.5f) ? -1.0f : labv;

    // ---- human images: per label n, front-most fragment with that label ----
    float4* ho = reinterpret_cast<float4*>(out + HUMAN_OFF) + (long long)p * 8;
#pragma unroll
    for (int n = 0; n < 8; ++n) {
        float4 res = make_float4(bgr, bgg, bgb, 0.0f);   // miss: zeros row => bg, alpha 0
        bool found = false;
#pragma unroll
        for (int k = 0; k < 8; ++k) {
            if (!found && z[k] >= 0.0f && lb[k] == n) {
                found = true;
                const float al = c[k].w;
                const float om = 1.0f - al;
                res = make_float4(c[k].x * al + bgr * om,
                                  c[k].y * al + bgg * om,
                                  c[k].z * al + bgb * om,
                                  al);
            }
        }
        ho[n] = res;
    }
}

extern "C" void kernel_launch(void* const* d_in, const int* in_sizes, int n_in,
                              void* d_out, int out_size)
{
    const float4* colors = (const float4*)d_in[0];
    const float4* zbuf4  = (const float4*)d_in[1];
    const int4*   labl4  = (const int4*)d_in[2];
    const float*  bg     = (const float*)d_in[3];
    float*        out    = (float*)d_out;

    const int threads = 256;
    const int blocks  = (NPIX + threads - 1) / threads;
    alpha_composite_kernel<<<blocks, threads>>>(colors, zbuf4, labl4, bg, out);
}

// round 4
// speedup vs baseline: 1.2410x; 1.2410x over previous
#include <cuda_runtime.h>

// B=4, H=512, W=512, K=8, BKG_DEPTH=100
// Inputs: colors f32[B,H,W,8,4], zbuf f32[B,H,W,8], labels i32[B,H,W,8], bg f32[3]
// Output (flat f32): image[NPIX*4] | depth[NPIX] | label[NPIX] | human[NPIX*8*4]

constexpr int   NPIX      = 4 * 512 * 512;     // 1,048,576
constexpr float BKG_DEPTH = 100.0f;

constexpr long long IMG_OFF   = 0;
constexpr long long DEPTH_OFF = (long long)NPIX * 4;
constexpr long long LABEL_OFF = DEPTH_OFF + NPIX;
constexpr long long HUMAN_OFF = LABEL_OFF + NPIX;

constexpr int BLOCK = 256;   // pixels per block == threads per block

__global__ void __launch_bounds__(BLOCK)
alpha_composite_kernel(const float4* __restrict__ colors,   // [NPIX*8] float4
                       const float4* __restrict__ zbuf4,    // [NPIX*2] float4
                       const int4*   __restrict__ labl4,    // [NPIX*2] int4
                       const float*  __restrict__ bg,       // [3]
                       float*        __restrict__ out)
{
    // 32 KB staging buffer: 256 pixels x 8 float4, XOR-swizzled so both the
    // coalesced fill/drain and the per-pixel gather/scatter are conflict-free.
    // slot(q,j) = q*8 + (j ^ (q&7))
    __shared__ float4 sbuf[BLOCK * 8];

    const int tid = threadIdx.x;
    const int p   = blockIdx.x * BLOCK + tid;          // this thread's pixel

    const float bgr = __ldg(bg + 0);
    const float bgg = __ldg(bg + 1);
    const float bgb = __ldg(bg + 2);

    // ---- Phase 1: coalesced load of colors into swizzled smem ----
    {
        const long long base = (long long)blockIdx.x * BLOCK * 8;  // float4 units
#pragma unroll
        for (int it = 0; it < 8; ++it) {
            const int idx = it * BLOCK + tid;          // 0..2047, coalesced
            const float4 v = colors[base + idx];
            const int q = idx >> 3;                    // pixel within block
            const int j = idx & 7;                     // layer
            sbuf[q * 8 + (j ^ (q & 7))] = v;
        }
    }
    __syncthreads();

    // ---- per-pixel gather from smem (conflict-free via swizzle) ----
    float4 c[8];
#pragma unroll
    for (int k = 0; k < 8; ++k)
        c[k] = sbuf[tid * 8 + (k ^ (tid & 7))];

    // zbuf / labels: direct loads (32B lane stride; modest wavefront cost)
    float z[8];
    {
        const float4 z0 = zbuf4[(long long)p * 2 + 0];
        const float4 z1 = zbuf4[(long long)p * 2 + 1];
        z[0] = z0.x; z[1] = z0.y; z[2] = z0.z; z[3] = z0.w;
        z[4] = z1.x; z[5] = z1.y; z[6] = z1.z; z[7] = z1.w;
    }
    int lb[8];
    {
        const int4 l0 = labl4[(long long)p * 2 + 0];
        const int4 l1 = labl4[(long long)p * 2 + 1];
        lb[0] = l0.x; lb[1] = l0.y; lb[2] = l0.z; lb[3] = l0.w;
        lb[4] = l1.x; lb[5] = l1.y; lb[6] = l1.z; lb[7] = l1.w;
    }

    // ---- back-to-front composite scan (layer 7 first, layer 0 last) ----
    float r = bgr, g = bgg, b = bgb;
    float a = 0.0f;
    float d = BKG_DEPTH;
    float labv = 8.0f;    // sentinel = K

#pragma unroll
    for (int k = 7; k >= 0; --k) {
        const float al = c[k].w;
        const float om = 1.0f - al;
        r = c[k].x * al + r * om;
        g = c[k].y * al + g * om;
        b = c[k].z * al + b * om;
        a = fmaxf(al, a);
        if (z[k] > 0.0f)               d    = z[k] * al + d * om;
        if (z[k] >= 0.0f && al > 0.5f) labv = (float)lb[k];  // z<0 => NaN => keep
    }

    reinterpret_cast<float4*>(out + IMG_OFF)[p] = make_float4(r, g, b, a);
    out[DEPTH_OFF + p] = d;
    out[LABEL_OFF + p] = (labv > 7.5f) ? -1.0f : labv;

    // ---- Phase 2: human images into swizzled smem (own slots only; no sync
    //      needed before this — only this thread read these slots above) ----
#pragma unroll
    for (int n = 0; n < 8; ++n) {
        float4 res = make_float4(bgr, bgg, bgb, 0.0f);   // miss -> (bg, 0)
        bool found = false;
#pragma unroll
        for (int k = 0; k < 8; ++k) {
            if (!found && z[k] >= 0.0f && lb[k] == n) {
                found = true;
                const float al = c[k].w;
                const float om = 1.0f - al;
                res = make_float4(c[k].x * al + bgr * om,
                                  c[k].y * al + bgg * om,
                                  c[k].z * al + bgb * om,
                                  al);
            }
        }
        sbuf[tid * 8 + (n ^ (tid & 7))] = res;
    }
    __syncthreads();

    // ---- coalesced drain of human images ----
    {
        float4* ho = reinterpret_cast<float4*>(out + HUMAN_OFF);
        const long long base = (long long)blockIdx.x * BLOCK * 8;   // float4 units
#pragma unroll
        for (int it = 0; it < 8; ++it) {
            const int idx = it * BLOCK + tid;          // coalesced
            const int q = idx >> 3;
            const int j = idx & 7;
            ho[base + idx] = sbuf[q * 8 + (j ^ (q & 7))];
        }
    }
}

extern "C" void kernel_launch(void* const* d_in, const int* in_sizes, int n_in,
                              void* d_out, int out_size)
{
    const float4* colors = (const float4*)d_in[0];
    const float4* zbuf4  = (const float4*)d_in[1];
    const int4*   labl4  = (const int4*)d_in[2];
    const float*  bg     = (const float*)d_in[3];
    float*        out    = (float*)d_out;

    alpha_composite_kernel<<<NPIX / BLOCK, BLOCK>>>(colors, zbuf4, labl4, bg, out);
}

// round 5
// speedup vs baseline: 1.3529x; 1.0902x over previous
#include <cuda_runtime.h>
#include <cstdint>

// B=4, H=512, W=512, K=8, BKG_DEPTH=100
// Inputs: colors f32[B,H,W,8,4], zbuf f32[B,H,W,8], labels i32[B,H,W,8], bg f32[3]
// Output (flat f32): image[NPIX*4] | depth[NPIX] | label[NPIX] | human[NPIX*8*4]

constexpr int   NPIX      = 4 * 512 * 512;     // 1,048,576
constexpr float BKG_DEPTH = 100.0f;

constexpr long long IMG_OFF   = 0;
constexpr long long DEPTH_OFF = (long long)NPIX * 4;
constexpr long long LABEL_OFF = DEPTH_OFF + NPIX;
constexpr long long HUMAN_OFF = LABEL_OFF + NPIX;

constexpr int BLOCK = 256;   // pixels per block == threads per block

__global__ void __launch_bounds__(BLOCK, 4)
alpha_composite_kernel(const float4* __restrict__ colors,   // [NPIX*8] float4
                       const float4* __restrict__ zbuf4,    // [NPIX*2] float4
                       const int4*   __restrict__ labl4,    // [NPIX*2] int4
                       const float*  __restrict__ bg,       // [3]
                       float*        __restrict__ out)
{
    // 32 KB staging buffer, XOR-swizzled: slot(q,j) = q*8 + (j ^ (q&7)).
    // Conflict-free for both the coalesced fill/drain (quarter-warp shares q,
    // j distinct) and the per-pixel strided access (tid*8 base ≡ bank 0,
    // x = j^(tid&7) distinct across quarter-warp).
    __shared__ float4 sbuf[BLOCK * 8];
    // Per-pixel nibble table: nibble n = first layer k with label n (0xF = miss)
    __shared__ unsigned stab[BLOCK];

    const int tid = threadIdx.x;
    const int p   = blockIdx.x * BLOCK + tid;
    const long long fbase = (long long)blockIdx.x * BLOCK * 8;  // fragment (float4) base

    // ---- Phase 1: cp.async color fill (no register staging) ----
    {
#pragma unroll
        for (int it = 0; it < 8; ++it) {
            const int idx = it * BLOCK + tid;              // coalesced
            const int q = idx >> 3, j = idx & 7;
            const uint32_t saddr =
                (uint32_t)__cvta_generic_to_shared(&sbuf[q * 8 + (j ^ (q & 7))]);
            const float4* gptr = colors + fbase + idx;
            asm volatile("cp.async.cg.shared.global [%0], [%1], 16;\n"
                         :: "r"(saddr), "l"(gptr));
        }
        asm volatile("cp.async.commit_group;\n");
    }

    // Overlap: z / labels / bg loads while cp.async is in flight
    const float4 z0 = zbuf4[(long long)p * 2 + 0];
    const float4 z1 = zbuf4[(long long)p * 2 + 1];
    const int4   l0 = labl4[(long long)p * 2 + 0];
    const int4   l1 = labl4[(long long)p * 2 + 1];
    const float bgr = __ldg(bg + 0);
    const float bgg = __ldg(bg + 1);
    const float bgb = __ldg(bg + 2);

    const float zz[8] = { z0.x, z0.y, z0.z, z0.w, z1.x, z1.y, z1.z, z1.w };
    const int   ll[8] = { l0.x, l0.y, l0.z, l0.w, l1.x, l1.y, l1.z, l1.w };

    asm volatile("cp.async.wait_group 0;\n");
    __syncthreads();

    // ---- Phase 2: fused back-to-front scan + blend (in-place overwrite) ----
    float r = bgr, g = bgg, b = bgb;
    float a = 0.0f;
    float d = BKG_DEPTH;
    float labv = -1.0f;          // miss sentinel maps straight to output -1
    unsigned T = 0xFFFFFFFFu;    // 8 nibbles, 0xF = miss

#pragma unroll
    for (int k = 7; k >= 0; --k) {
        const int slot = tid * 8 + (k ^ (tid & 7));
        const float4 c = sbuf[slot];
        const float al = c.w;
        const float om = 1.0f - al;

        r = c.x * al + r * om;
        g = c.y * al + g * om;
        b = c.z * al + b * om;
        a = fmaxf(al, a);

        const bool znn = !(zz[k] < 0.0f);          // matches reference NaN handling
        if (zz[k] > 0.0f)       d    = zz[k] * al + d * om;
        if (znn && al > 0.5f)   labv = (float)ll[k];

        // human blend overwrites the color slot (this thread is sole owner)
        sbuf[slot] = make_float4(c.x * al + bgr * om,
                                 c.y * al + bgg * om,
                                 c.z * al + bgb * om,
                                 al);

        // first-k table: descending k loop => smallest valid k wins per label
        if (znn) {
            const int n = ll[k] & 7;
            T = (T & ~(0xFu << (4 * n))) | ((unsigned)k << (4 * n));
        }
    }
    stab[tid] = T;

    reinterpret_cast<float4*>(out + IMG_OFF)[p] = make_float4(r, g, b, a);
    out[DEPTH_OFF + p] = d;
    out[LABEL_OFF + p] = labv;

    __syncthreads();

    // ---- Phase 3: coalesced drain of human images via nibble-table gather ----
    {
        float4* ho = reinterpret_cast<float4*>(out + HUMAN_OFF);
#pragma unroll
        for (int it = 0; it < 8; ++it) {
            const int idx = it * BLOCK + tid;              // coalesced
            const int q = idx >> 3, n = idx & 7;           // pixel q, label n
            const unsigned Tq = stab[q];                   // broadcast within quarter-warp
            const unsigned kk = (Tq >> (4 * n)) & 0xFu;
            float4 v;
            if (kk < 8u) {
                v = sbuf[q * 8 + ((int)kk ^ (q & 7))];     // broadcast or distinct-bank
            } else {
                v = make_float4(bgr, bgg, bgb, 0.0f);      // miss -> (bg, 0)
            }
            ho[fbase + idx] = v;
        }
    }
}

extern "C" void kernel_launch(void* const* d_in, const int* in_sizes, int n_in,
                              void* d_out, int out_size)
{
    const float4* colors = (const float4*)d_in[0];
    const float4* zbuf4  = (const float4*)d_in[1];
    const int4*   labl4  = (const int4*)d_in[2];
    const float*  bg     = (const float*)d_in[3];
    float*        out    = (float*)d_out;

    alpha_composite_kernel<<<NPIX / BLOCK, BLOCK>>>(colors, zbuf4, labl4, bg, out);
}